// round 16
// baseline (speedup 1.0000x reference)
#include <cuda_runtime.h>
#include <cstdint>

#define KTOP 500
#define CAND_MAX 4096
#define NBIN 4096
#define NTASK 336
#define SCAN_BUF 2048
#define NTH 512

// ---------------- global scratch ----------------
__device__ unsigned long long g_cand[NTASK][CAND_MAX];
__device__ int g_cnt[NTASK];    // zero at load; restored at end of fused phase
__device__ int g_done[NTASK];   // chunk-completion tickets; restored likewise

__device__ __forceinline__ unsigned int mapf(float v) {
    unsigned int u = __float_as_uint(v);
    return (u & 0x80000000u) ? ~u : (u | 0x80000000u);
}
__device__ __forceinline__ float unmapf(unsigned int u) {
    return __uint_as_float((u & 0x80000000u) ? (u ^ 0x80000000u) : ~u);
}

struct Fused {
    union {
        unsigned long long cand[CAND_MAX];                               // 32768 B (also scan buffer)
        struct { unsigned int hist[NBIN]; unsigned int scan[NTH]; } h;
        unsigned long long sup[KTOP][8];                                 // 32000 B
    } big;
    float bx1[512], by1[512], bx2[512], by2[512], ar[512];
    int cellcnt[1024];
    int cellstart[1024];
    unsigned short order[512];
    unsigned short cellid[512];
    unsigned long long keepw[8];
    unsigned long long supmark[8];
    float warpred[16][5];
    float red[5];
    int wtot[16];
    int T, cntAbove, cnt_s;
    int scan_cnt, scan_base, last;
};

__device__ void find_thr(Fused& S, int need, int tid, int& T_out, int& above_out) {
    int t8 = tid * 8;
    unsigned hh[8];
    unsigned sum = 0;
    #pragma unroll
    for (int e = 0; e < 8; e++) { hh[e] = S.big.h.hist[t8 + e]; sum += hh[e]; }
    S.big.h.scan[tid] = sum;
    __syncthreads();
    for (int off = 1; off < NTH; off <<= 1) {
        unsigned add = (tid + off < NTH) ? S.big.h.scan[tid + off] : 0u;
        __syncthreads();
        S.big.h.scan[tid] += add;
        __syncthreads();
    }
    unsigned sfx = S.big.h.scan[tid];
    unsigned nxt = (tid < NTH - 1) ? S.big.h.scan[tid + 1] : 0u;
    if (sfx >= (unsigned)need && nxt < (unsigned)need) {
        unsigned c = nxt;
        for (int b = 7; b >= 0; b--) {
            if (c + hh[b] >= (unsigned)need) { S.T = t8 + b; S.cntAbove = (int)c; break; }
            c += hh[b];
        }
    }
    __syncthreads();
    T_out = S.T;
    above_out = S.cntAbove;
}

__device__ __forceinline__ float wmaxf(float v) {
    #pragma unroll
    for (int o = 16; o; o >>= 1) v = fmaxf(v, __shfl_xor_sync(0xFFFFFFFFu, v, o));
    return v;
}
__device__ __forceinline__ float wminf(float v) {
    #pragma unroll
    for (int o = 16; o; o >>= 1) v = fminf(v, __shfl_xor_sync(0xFFFFFFFFu, v, o));
    return v;
}

// ---------------- single merged kernel: scan chunks + last-arriver fused ----------------
__global__ __launch_bounds__(NTH, 4) void k_all(
    const float* __restrict__ cls3, const float* __restrict__ cls4, const float* __restrict__ cls5,
    const float* __restrict__ reg3, const float* __restrict__ reg4, const float* __restrict__ reg5,
    float* __restrict__ out)
{
    extern __shared__ unsigned char sraw[];
    Fused& S = *reinterpret_cast<Fused*>(sraw);
    const int tid = threadIdx.x;
    const int lane = tid & 31;
    const int wid = tid >> 5;

    // block -> (task, chunk, nchunk): lev0 tasks get 4 chunks, lev1/lev2 get 1
    int b = blockIdx.x;
    int task, chunk, nchunk;
    if (b < 448)      { task = b >> 2;          chunk = b & 3; nchunk = 4; }
    else if (b < 560) { task = 112 + (b - 448); chunk = 0;     nchunk = 1; }
    else              { task = 224 + (b - 560); chunk = 0;     nchunk = 1; }

    int lev = (task < 112) ? 0 : ((task < 224) ? 1 : 2);
    int tt = task - lev * 112;
    int img = tt / 7;
    int cls = tt % 7;
    const int H = 192 >> lev;
    const int HW = H * H;
    const int W = H;
    const float stride = (float)(8 << lev);
    const float asize  = (float)(16 << lev);

    const float* clsP = (lev == 0) ? cls3 : ((lev == 1) ? cls4 : cls5);
    const float* regP = (lev == 0) ? reg3 : ((lev == 1) ? reg4 : reg5);
    const float* plane0 = clsP + (size_t)(img * 24 + 0 * 8 + cls + 1) * HW;
    const float* plane1 = clsP + (size_t)(img * 24 + 1 * 8 + cls + 1) * HW;
    const float* plane2 = clsP + (size_t)(img * 24 + 2 * 8 + cls + 1) * HW;
    const float* planes[3] = { plane0, plane1, plane2 };

    // ================= scan phase (all blocks) =================
    float thf = (lev == 0) ? -1.55f : ((lev == 1) ? -2.10f : -2.80f);

    if (tid == 0) S.scan_cnt = 0;
    __syncthreads();

    {
        int nv4 = HW >> 2;
        int start = chunk * 512 + tid;
        int sstride = nchunk * 512;
        const float4* p0 = (const float4*)plane0;
        const float4* p1 = (const float4*)plane1;
        const float4* p2 = (const float4*)plane2;
        for (int i4 = start; i4 < nv4; i4 += sstride) {
            float4 v0 = p0[i4];
            float4 v1 = p1[i4];
            float4 v2 = p2[i4];
            #pragma unroll
            for (int a = 0; a < 3; a++) {
                float4 v = (a == 0) ? v0 : (a == 1) ? v1 : v2;
                #pragma unroll
                for (int e = 0; e < 4; e++) {
                    float f = (e == 0) ? v.x : (e == 1) ? v.y : (e == 2) ? v.z : v.w;
                    if (f > thf) {
                        int pos = atomicAdd(&S.scan_cnt, 1);
                        if (pos < SCAN_BUF) {
                            unsigned n = (unsigned)((i4 * 4 + e) * 3 + a);
                            S.big.cand[pos] = ((unsigned long long)mapf(f) << 32)
                                            | (unsigned long long)(~n);
                        }
                    }
                }
            }
        }
    }
    __syncthreads();

    int scnt = S.scan_cnt;
    if (tid == 0) {
        int rep = (scnt > SCAN_BUF) ? scnt + 100000 : scnt;  // poison -> exact fallback
        S.scan_base = atomicAdd(&g_cnt[task], rep);
    }
    __syncthreads();
    {
        int base = S.scan_base;
        int nf = min(scnt, SCAN_BUF);
        for (int i = tid; i < nf; i += NTH) {
            int p = base + i;
            if (p < CAND_MAX) g_cand[task][p] = S.big.cand[i];
        }
    }
    __threadfence();   // release: this thread's g_cand/g_cnt writes visible device-wide
    __syncthreads();
    if (tid == 0) {
        int old = atomicAdd(&g_done[task], 1);
        S.last = (old == nchunk - 1) ? 1 : 0;
    }
    __syncthreads();
    if (!S.last) return;
    __threadfence();   // acquire side after winning ticket

    // ================= fused phase (last arriver per task) =================
    if (tid < 8) { S.keepw[tid] = 0ull; S.supmark[tid] = 0ull; }

    int cnt = g_cnt[task];

    if (cnt >= KTOP && cnt <= CAND_MAX) {
        for (int i = tid; i < cnt; i += NTH) S.big.cand[i] = g_cand[task][i];
        __syncthreads();
    } else {
        // exact fallback: 12-bit histogram select over raw planes
        for (int i = tid; i < NBIN; i += NTH) S.big.h.hist[i] = 0;
        __syncthreads();
        for (int a = 0; a < 3; a++) {
            const float* p = planes[a];
            for (int i = tid; i < HW; i += NTH) {
                unsigned u = mapf(p[i]);
                int bin = (int)(u >> 20);
                unsigned m = __match_any_sync(__activemask(), bin);
                int leader = __ffs(m) - 1;
                if (lane == leader) atomicAdd(&S.big.h.hist[bin], (unsigned)__popc(m));
            }
        }
        __syncthreads();
        int T, above;
        find_thr(S, KTOP, tid, T, above);
        if (tid == 0) S.cnt_s = 0;
        __syncthreads();
        for (int a = 0; a < 3; a++) {
            const float* p = planes[a];
            for (int i = tid; i < HW; i += NTH) {
                unsigned u = mapf(p[i]);
                if ((int)(u >> 20) >= T) {
                    int pos = atomicAdd(&S.cnt_s, 1);
                    if (pos < CAND_MAX) {
                        unsigned n = (unsigned)(i * 3 + a);
                        S.big.cand[pos] = ((unsigned long long)u << 32) | (unsigned long long)(~n);
                    }
                }
            }
        }
        __syncthreads();
        cnt = S.cnt_s;

        if (cnt > CAND_MAX) {
            for (int i = tid; i < NBIN; i += NTH) S.big.h.hist[i] = 0;
            __syncthreads();
            for (int a = 0; a < 3; a++) {
                const float* p = planes[a];
                for (int i = tid; i < HW; i += NTH) {
                    unsigned u = mapf(p[i]);
                    if ((int)(u >> 20) == T)
                        atomicAdd(&S.big.h.hist[(u >> 8) & 0xFFFu], 1u);
                }
            }
            __syncthreads();
            int T2, ab2;
            find_thr(S, KTOP - above, tid, T2, ab2);
            if (tid == 0) S.cnt_s = 0;
            __syncthreads();
            for (int a = 0; a < 3; a++) {
                const float* p = planes[a];
                for (int i = tid; i < HW; i += NTH) {
                    unsigned u = mapf(p[i]);
                    int bin = (int)(u >> 20);
                    if (bin > T || (bin == T && (int)((u >> 8) & 0xFFFu) >= T2)) {
                        int pos = atomicAdd(&S.cnt_s, 1);
                        if (pos < CAND_MAX) {
                            unsigned n = (unsigned)(i * 3 + a);
                            S.big.cand[pos] = ((unsigned long long)u << 32) | (unsigned long long)(~n);
                        }
                    }
                }
            }
            __syncthreads();
            cnt = S.cnt_s;
        }
        if (cnt > CAND_MAX) cnt = CAND_MAX;
    }

    // ---------- sort descending ----------
    if (cnt <= 1024) {
        // hybrid bitonic: 2 elems/thread in regs; j>=64 via smem,
        // j==32 in-thread, j<=16 via shfl. Global rule desc = ((i & k) == 0).
        for (int i = cnt + tid; i < 1024; i += NTH) S.big.cand[i] = 0ull;
        __syncthreads();

        const int rbase = wid << 6;
        const int i_lo = rbase + lane;
        const int i_hi = rbase + lane + 32;
        unsigned long long vlo = S.big.cand[i_lo];
        unsigned long long vhi = S.big.cand[i_hi];

        #define SHFL_STEP(k, j) do {                                               \
            unsigned long long plo = __shfl_xor_sync(0xFFFFFFFFu, vlo, (j));       \
            unsigned long long phi = __shfl_xor_sync(0xFFFFFFFFu, vhi, (j));       \
            bool low = ((lane & (j)) == 0);                                        \
            bool wl = (low == ((i_lo & (k)) == 0));                                \
            bool wh = (low == ((i_hi & (k)) == 0));                                \
            vlo = wl ? (vlo > plo ? vlo : plo) : (vlo < plo ? vlo : plo);          \
            vhi = wh ? (vhi > phi ? vhi : phi) : (vhi < phi ? vhi : phi);          \
        } while (0)

        #define INTHREAD_STEP(k) do {                                              \
            bool desc = ((i_lo & (k)) == 0);                                       \
            bool sw = desc ? (vlo < vhi) : (vlo > vhi);                            \
            if (sw) { unsigned long long t = vlo; vlo = vhi; vhi = t; }            \
        } while (0)

        #pragma unroll
        for (int k = 2; k <= 32; k <<= 1) {
            #pragma unroll
            for (int j = k >> 1; j >= 1; j >>= 1) SHFL_STEP(k, j);
        }
        INTHREAD_STEP(64);
        #pragma unroll
        for (int j = 16; j >= 1; j >>= 1) SHFL_STEP(64, j);

        #pragma unroll
        for (int k = 128; k <= 1024; k <<= 1) {
            S.big.cand[i_lo] = vlo;
            S.big.cand[i_hi] = vhi;
            for (int j = k >> 1; j >= 64; j >>= 1) {
                __syncthreads();
                #pragma unroll
                for (int t2 = 0; t2 < 2; t2++) {
                    int i = tid + t2 * 512;
                    int ixj = i ^ j;
                    if (ixj > i) {
                        unsigned long long a = S.big.cand[i], b2 = S.big.cand[ixj];
                        bool sw = ((i & k) == 0) ? (a < b2) : (a > b2);
                        if (sw) { S.big.cand[i] = b2; S.big.cand[ixj] = a; }
                    }
                }
            }
            __syncthreads();
            vlo = S.big.cand[i_lo];
            vhi = S.big.cand[i_hi];
            INTHREAD_STEP(k);
            #pragma unroll
            for (int j = 16; j >= 1; j >>= 1) SHFL_STEP(k, j);
        }
        S.big.cand[i_lo] = vlo;
        S.big.cand[i_hi] = vhi;
        __syncthreads();
        #undef SHFL_STEP
        #undef INTHREAD_STEP
    } else {
        int M = 2048;
        while (M < cnt) M <<= 1;
        for (int i = cnt + tid; i < M; i += NTH) S.big.cand[i] = 0ull;
        __syncthreads();
        for (int k = 2; k <= M; k <<= 1) {
            for (int j = k >> 1; j > 0; j >>= 1) {
                for (int i = tid; i < M; i += NTH) {
                    int ixj = i ^ j;
                    if (ixj > i) {
                        unsigned long long a = S.big.cand[i], b2 = S.big.cand[ixj];
                        bool sw = ((i & k) == 0) ? (a < b2) : (a > b2);
                        if (sw) { S.big.cand[i] = b2; S.big.cand[ixj] = a; }
                    }
                }
                __syncthreads();
            }
        }
    }

    // ---------- decode top-500, write boxes/scores/labels, stash in smem ----------
    long long tbase = (long long)((lev * 16 + img) * 7 + cls) * KTOP;
    float4* obox4 = (float4*)(out + tbase * 4);
    float* osc   = out + 672000 + tbase;
    float* olab  = out + 1008000 + tbase;

    {
        int r = tid;
        bool valid_bit = false;
        float bx1v = 0.0f, by1v = 0.0f, bx2v = 0.0f, by2v = 0.0f;
        if (r < KTOP) {
            unsigned long long key = S.big.cand[r];
            unsigned u = (unsigned)(key >> 32);
            unsigned n = ~((unsigned)key);
            float logit = unmapf(u);
            float score = __fdividef(1.0f, 1.0f + __expf(-logit));

            unsigned a = n % 3u;
            unsigned p = n / 3u;
            int sh = 6 - lev;             // W = 3 << sh
            unsigned y = (p >> sh) / 3u;  // p / W via const-div
            unsigned x = p - y * (unsigned)W;
            float sqv = (a == 0) ? 0.70710678118654752f : ((a == 1) ? 1.0f : 1.41421356237309505f);
            float wa = asize * sqv;
            float ha = asize / sqv;
            float cxa = ((float)x + 0.5f) * stride;
            float cya = ((float)y + 0.5f) * stride;

            size_t rb = (size_t)(img * 12 + a * 4) * HW + (size_t)p;
            float dx = regP[rb];
            float dy = regP[rb + HW];
            float dw = regP[rb + 2 * (size_t)HW];
            float dh = regP[rb + 3 * (size_t)HW];

            float cx = dx * wa + cxa;
            float cy = dy * ha + cya;
            float bw = __expf(dw) * wa;
            float bh = __expf(dh) * ha;
            bx1v = cx - 0.5f * bw; by1v = cy - 0.5f * bh;
            bx2v = cx + 0.5f * bw; by2v = cy + 0.5f * bh;

            obox4[r] = make_float4(bx1v, by1v, bx2v, by2v);
            osc[r] = score;
            olab[r] = (float)cls;
            valid_bit = (score > 0.05f);
        }
        unsigned bmask = __ballot_sync(0xFFFFFFFFu, valid_bit);
        if (lane == 0 && bmask)
            atomicOr(&S.keepw[tid >> 6], (unsigned long long)bmask << ((tid >> 5 & 1) * 32));
        __syncthreads();   // cand reads complete before sup (aliased) is zeroed below
        S.bx1[tid] = bx1v; S.by1[tid] = by1v; S.bx2[tid] = bx2v; S.by2[tid] = by2v;
        S.ar[tid]  = (bx2v - bx1v) * (by2v - by1v);
    }

    // ---------- zero sup matrix (reuses cand region) + hash init ----------
    for (int i = tid; i < KTOP * 8; i += NTH)
        (&S.big.sup[0][0])[i] = 0ull;
    for (int i = tid; i < 1024; i += NTH) S.cellcnt[i] = 0;
    __syncthreads();

    // ---------- spatial hash build ----------
    bool real = (tid < KTOP);
    float cx = 0.5f * (S.bx1[tid] + S.bx2[tid]);
    float cy = 0.5f * (S.by1[tid] + S.by2[tid]);
    float ext = fmaxf(S.bx2[tid] - S.bx1[tid], S.by2[tid] - S.by1[tid]);
    float rminx = real ? cx : 1e30f, rmaxx = real ? cx : -1e30f;
    float rminy = real ? cy : 1e30f, rmaxy = real ? cy : -1e30f;
    float rext  = real ? ext : 0.0f;
    rminx = wminf(rminx); rmaxx = wmaxf(rmaxx);
    rminy = wminf(rminy); rmaxy = wmaxf(rmaxy);
    rext  = wmaxf(rext);
    if (lane == 0) {
        S.warpred[wid][0] = rminx; S.warpred[wid][1] = rmaxx;
        S.warpred[wid][2] = rminy; S.warpred[wid][3] = rmaxy;
        S.warpred[wid][4] = rext;
    }
    __syncthreads();
    if (wid == 0) {
        float a0 = (lane < 16) ? S.warpred[lane][0] : 1e30f;
        float a1 = (lane < 16) ? S.warpred[lane][1] : -1e30f;
        float a2 = (lane < 16) ? S.warpred[lane][2] : 1e30f;
        float a3 = (lane < 16) ? S.warpred[lane][3] : -1e30f;
        float a4 = (lane < 16) ? S.warpred[lane][4] : 0.0f;
        a0 = wminf(a0); a1 = wmaxf(a1); a2 = wminf(a2); a3 = wmaxf(a3); a4 = wmaxf(a4);
        if (lane == 0) {
            S.red[0] = a0; S.red[1] = a1; S.red[2] = a2; S.red[3] = a3; S.red[4] = a4;
        }
    }
    __syncthreads();

    float minx = S.red[0], miny = S.red[2];
    float rx = S.red[1] - minx, ry = S.red[3] - miny;
    float cs = fmaxf(fmaxf(S.red[4], fmaxf(rx, ry) * (1.0f / 31.0f)), 1.0f) * 1.0001f;
    float inv_cs = 1.0f / cs;
    int ncx = min(32, (int)(rx * inv_cs) + 1);
    int ncy = min(32, (int)(ry * inv_cs) + 1);

    int cix = 0, ciy = 0;
    if (real) {
        cix = min(ncx - 1, max(0, (int)((cx - minx) * inv_cs)));
        ciy = min(ncy - 1, max(0, (int)((cy - miny) * inv_cs)));
        int cid = ciy * 32 + cix;
        S.cellid[tid] = (unsigned short)cid;
        atomicAdd(&S.cellcnt[cid], 1);
    }
    __syncthreads();

    // exclusive scan of 1024 cell counts (512 threads x 2)
    {
        int c0 = S.cellcnt[2 * tid], c1 = S.cellcnt[2 * tid + 1];
        int s = c0 + c1;
        int incl = s;
        #pragma unroll
        for (int o = 1; o < 32; o <<= 1) {
            int n = __shfl_up_sync(0xFFFFFFFFu, incl, o);
            if (lane >= o) incl += n;
        }
        if (lane == 31) S.wtot[wid] = incl;
        __syncthreads();
        if (wid == 0) {
            int t = (lane < 16) ? S.wtot[lane] : 0;
            int ti = t;
            #pragma unroll
            for (int o = 1; o < 32; o <<= 1) {
                int n = __shfl_up_sync(0xFFFFFFFFu, ti, o);
                if (lane >= o) ti += n;
            }
            if (lane < 16) S.wtot[lane] = ti - t;
        }
        __syncthreads();
        int woff = S.wtot[wid];
        int excl = woff + incl - s;
        S.cellstart[2 * tid] = excl;
        S.cellstart[2 * tid + 1] = excl + c0;
    }
    __syncthreads();

    if (real) {
        int pos = atomicAdd(&S.cellstart[S.cellid[tid]], 1);
        S.order[pos] = (unsigned short)tid;
    }
    __syncthreads();

    // sparse pair search: 3x3 neighbor cells, only j > i, set bit on IoU > 0.5
    if (real) {
        int i = tid;
        float ix1 = S.bx1[i], iy1 = S.by1[i], ix2 = S.bx2[i], iy2 = S.by2[i];
        float ai = S.ar[i];
        bool any = false;
        for (int dy = -1; dy <= 1; dy++) {
            int yy = ciy + dy;
            if (yy < 0 || yy >= ncy) continue;
            for (int dxl = -1; dxl <= 1; dxl++) {
                int xx = cix + dxl;
                if (xx < 0 || xx >= ncx) continue;
                int c = yy * 32 + xx;
                int e = S.cellstart[c];
                int b2 = e - S.cellcnt[c];
                for (int k = b2; k < e; k++) {
                    int j = S.order[k];
                    if (j <= i) continue;
                    float xx1 = fmaxf(ix1, S.bx1[j]);
                    float yy1 = fmaxf(iy1, S.by1[j]);
                    float xx2 = fminf(ix2, S.bx2[j]);
                    float yy2 = fminf(iy2, S.by2[j]);
                    float inter = fmaxf(xx2 - xx1, 0.0f) * fmaxf(yy2 - yy1, 0.0f);
                    if (3.0f * inter > ai + S.ar[j]) {
                        atomicOr(&S.big.sup[i][j >> 6], 1ull << (j & 63));
                        any = true;
                    }
                }
            }
        }
        if (any) atomicOr(&S.supmark[i >> 6], 1ull << (i & 63));
    }
    __syncthreads();

    // sparse greedy: visit only alive suppressor rows in index order (exact)
    if (tid == 0) {
        unsigned long long dropped[8] = {0,0,0,0,0,0,0,0};
        for (int w = 0; w < 8; w++) {
            unsigned long long rem = S.supmark[w] & S.keepw[w];
            while (true) {
                unsigned long long r2 = rem & ~dropped[w];
                if (!r2) break;
                int b2 = __ffsll((long long)r2) - 1;
                rem &= ~(1ull << b2);
                int i = (w << 6) + b2;
                #pragma unroll
                for (int w2 = 0; w2 < 8; w2++) dropped[w2] |= S.big.sup[i][w2];
            }
        }
        #pragma unroll
        for (int w = 0; w < 8; w++) S.keepw[w] &= ~dropped[w];
    }
    __syncthreads();

    float* okeep = out + 840000 + tbase;
    for (int r = tid; r < KTOP; r += NTH)
        okeep[r] = ((S.keepw[r >> 6] >> (r & 63)) & 1ull) ? 1.0f : 0.0f;
    if (tid == 0) { g_cnt[task] = 0; g_done[task] = 0; }  // restore for next replay
}

// ---------------- launcher ----------------
extern "C" void kernel_launch(void* const* d_in, const int* in_sizes, int n_in,
                              void* d_out, int out_size) {
    const float *cls3 = nullptr, *cls4 = nullptr, *cls5 = nullptr;
    const float *reg3 = nullptr, *reg4 = nullptr, *reg5 = nullptr;
    for (int i = 0; i < n_in; i++) {
        switch (in_sizes[i]) {
            case 14155776: cls3 = (const float*)d_in[i]; break;
            case 7077888:  reg3 = (const float*)d_in[i]; break;
            case 3538944:  cls4 = (const float*)d_in[i]; break;
            case 1769472:  reg4 = (const float*)d_in[i]; break;
            case 884736:   cls5 = (const float*)d_in[i]; break;
            case 442368:   reg5 = (const float*)d_in[i]; break;
        }
    }
    float* out = (float*)d_out;
    cudaFuncSetAttribute(k_all, cudaFuncAttributeMaxDynamicSharedMemorySize,
                         (int)sizeof(Fused));
    k_all<<<672, NTH, sizeof(Fused)>>>(cls3, cls4, cls5, reg3, reg4, reg5, out);
}

// round 17
// speedup vs baseline: 1.0908x; 1.0908x over previous
#include <cuda_runtime.h>
#include <cstdint>

#define KTOP 500
#define CAND_MAX 4096
#define NBIN 4096
#define NTASK 336
#define SCAN_BUF 2048
#define NTH 512

// ---------------- global scratch ----------------
__device__ unsigned long long g_cand[NTASK][CAND_MAX];
__device__ int g_cnt[NTASK];   // zero at load; restored by k_fused

__device__ __forceinline__ unsigned int mapf(float v) {
    unsigned int u = __float_as_uint(v);
    return (u & 0x80000000u) ? ~u : (u | 0x80000000u);
}
__device__ __forceinline__ float unmapf(unsigned int u) {
    return __uint_as_float((u & 0x80000000u) ? (u ^ 0x80000000u) : ~u);
}

__device__ __forceinline__ void task_info(int task, int& lev, int& img, int& cls,
                                          int& H, int& HW) {
    lev = (task < 112) ? 0 : ((task < 224) ? 1 : 2);
    int tt = task - lev * 112;
    img = tt / 7;
    cls = tt % 7;
    H = 192 >> lev;
    HW = H * H;
}

// ---------------- kernel 1: streaming compaction, smem-buffered ----------------
__global__ __launch_bounds__(512, 4) void k_scan(
    const float* __restrict__ cls3, const float* __restrict__ cls4,
    const float* __restrict__ cls5)
{
    __shared__ unsigned long long s_buf[SCAN_BUF];
    __shared__ int s_cnt, s_base;

    int b = blockIdx.x;
    int task, chunk, nchunk;
    if (b < 448)      { task = b >> 2;          chunk = b & 3; nchunk = 4; }
    else if (b < 560) { task = 112 + (b - 448); chunk = 0;     nchunk = 1; }
    else              { task = 224 + (b - 560); chunk = 0;     nchunk = 1; }

    int lev, img, cls, H, HW;
    task_info(task, lev, img, cls, H, HW);

    const float* clsP = (lev == 0) ? cls3 : ((lev == 1) ? cls4 : cls5);
    float thf = (lev == 0) ? -1.55f : ((lev == 1) ? -2.10f : -2.80f);

    if (threadIdx.x == 0) s_cnt = 0;
    __syncthreads();

    int nv4 = HW >> 2;
    int start = chunk * 512 + threadIdx.x;
    int stride = nchunk * 512;

    const float4* p0 = (const float4*)(clsP + (size_t)(img * 24 + 0 * 8 + cls + 1) * HW);
    const float4* p1 = (const float4*)(clsP + (size_t)(img * 24 + 1 * 8 + cls + 1) * HW);
    const float4* p2 = (const float4*)(clsP + (size_t)(img * 24 + 2 * 8 + cls + 1) * HW);

    for (int i4 = start; i4 < nv4; i4 += stride) {
        float4 v0 = p0[i4];
        float4 v1 = p1[i4];
        float4 v2 = p2[i4];
        #pragma unroll
        for (int a = 0; a < 3; a++) {
            float4 v = (a == 0) ? v0 : (a == 1) ? v1 : v2;
            #pragma unroll
            for (int e = 0; e < 4; e++) {
                float f = (e == 0) ? v.x : (e == 1) ? v.y : (e == 2) ? v.z : v.w;
                if (f > thf) {
                    int pos = atomicAdd(&s_cnt, 1);
                    if (pos < SCAN_BUF) {
                        unsigned n = (unsigned)((i4 * 4 + e) * 3 + a);
                        s_buf[pos] = ((unsigned long long)mapf(f) << 32)
                                   | (unsigned long long)(~n);
                    }
                }
            }
        }
    }
    __syncthreads();

    int scnt = s_cnt;
    if (threadIdx.x == 0) {
        int rep = (scnt > SCAN_BUF) ? scnt + 100000 : scnt;  // poison -> exact fallback
        s_base = atomicAdd(&g_cnt[task], rep);
    }
    __syncthreads();
    int base = s_base;
    int nf = min(scnt, SCAN_BUF);
    for (int i = threadIdx.x; i < nf; i += 512) {
        int p = base + i;
        if (p < CAND_MAX) g_cand[task][p] = s_buf[i];
    }
}

// ---------------- kernel 2: fused select/sort/decode + spatial-hash NMS ----------------
struct Fused {
    union {
        unsigned long long cand[CAND_MAX];                               // 32768 B
        struct { unsigned int hist[NBIN]; unsigned int scan[NTH]; } h;   // 18432 B
        unsigned long long sup[KTOP][8];                                 // 32000 B
    } big;
    float bx1[512], by1[512], bx2[512], by2[512], ar[512];
    int cellcnt[1024];
    int cellstart[1024];
    unsigned short order[512];
    unsigned short cellid[512];
    unsigned long long keepw[8];
    unsigned long long supmark[8];
    float warpred[16][5];
    float red[5];
    int wtot[16];
    int T, cntAbove, cnt_s;
};

__device__ void find_thr(Fused& S, int need, int tid, int& T_out, int& above_out) {
    int t8 = tid * 8;
    unsigned hh[8];
    unsigned sum = 0;
    #pragma unroll
    for (int e = 0; e < 8; e++) { hh[e] = S.big.h.hist[t8 + e]; sum += hh[e]; }
    S.big.h.scan[tid] = sum;
    __syncthreads();
    for (int off = 1; off < NTH; off <<= 1) {
        unsigned add = (tid + off < NTH) ? S.big.h.scan[tid + off] : 0u;
        __syncthreads();
        S.big.h.scan[tid] += add;
        __syncthreads();
    }
    unsigned sfx = S.big.h.scan[tid];
    unsigned nxt = (tid < NTH - 1) ? S.big.h.scan[tid + 1] : 0u;
    if (sfx >= (unsigned)need && nxt < (unsigned)need) {
        unsigned c = nxt;
        for (int b = 7; b >= 0; b--) {
            if (c + hh[b] >= (unsigned)need) { S.T = t8 + b; S.cntAbove = (int)c; break; }
            c += hh[b];
        }
    }
    __syncthreads();
    T_out = S.T;
    above_out = S.cntAbove;
}

__device__ __forceinline__ float wmaxf(float v) {
    #pragma unroll
    for (int o = 16; o; o >>= 1) v = fmaxf(v, __shfl_xor_sync(0xFFFFFFFFu, v, o));
    return v;
}
__device__ __forceinline__ float wminf(float v) {
    #pragma unroll
    for (int o = 16; o; o >>= 1) v = fminf(v, __shfl_xor_sync(0xFFFFFFFFu, v, o));
    return v;
}

__global__ __launch_bounds__(NTH, 4) void k_fused(
    const float* __restrict__ cls3, const float* __restrict__ cls4, const float* __restrict__ cls5,
    const float* __restrict__ reg3, const float* __restrict__ reg4, const float* __restrict__ reg5,
    float* __restrict__ out)
{
    extern __shared__ unsigned char sraw[];
    Fused& S = *reinterpret_cast<Fused*>(sraw);
    const int tid = threadIdx.x;
    const int lane = tid & 31;
    const int wid = tid >> 5;

    int task = blockIdx.x;
    int lev, img, cls, H, HW;
    task_info(task, lev, img, cls, H, HW);
    const int W = H;
    const float stride = (float)(8 << lev);
    const float asize  = (float)(16 << lev);

    const float* clsP = (lev == 0) ? cls3 : ((lev == 1) ? cls4 : cls5);
    const float* regP = (lev == 0) ? reg3 : ((lev == 1) ? reg4 : reg5);
    const float* plane0 = clsP + (size_t)(img * 24 + 0 * 8 + cls + 1) * HW;
    const float* plane1 = clsP + (size_t)(img * 24 + 1 * 8 + cls + 1) * HW;
    const float* plane2 = clsP + (size_t)(img * 24 + 2 * 8 + cls + 1) * HW;
    const float* planes[3] = { plane0, plane1, plane2 };

    if (tid < 8) { S.keepw[tid] = 0ull; S.supmark[tid] = 0ull; }

    int cnt = g_cnt[task];

    if (cnt >= KTOP && cnt <= CAND_MAX) {
        for (int i = tid; i < cnt; i += NTH) S.big.cand[i] = g_cand[task][i];
        __syncthreads();
    } else {
        // exact fallback: 12-bit histogram select over raw planes
        for (int i = tid; i < NBIN; i += NTH) S.big.h.hist[i] = 0;
        __syncthreads();
        for (int a = 0; a < 3; a++) {
            const float* p = planes[a];
            for (int i = tid; i < HW; i += NTH) {
                unsigned u = mapf(p[i]);
                int bin = (int)(u >> 20);
                unsigned m = __match_any_sync(__activemask(), bin);
                int leader = __ffs(m) - 1;
                if (lane == leader) atomicAdd(&S.big.h.hist[bin], (unsigned)__popc(m));
            }
        }
        __syncthreads();
        int T, above;
        find_thr(S, KTOP, tid, T, above);
        if (tid == 0) S.cnt_s = 0;
        __syncthreads();
        for (int a = 0; a < 3; a++) {
            const float* p = planes[a];
            for (int i = tid; i < HW; i += NTH) {
                unsigned u = mapf(p[i]);
                if ((int)(u >> 20) >= T) {
                    int pos = atomicAdd(&S.cnt_s, 1);
                    if (pos < CAND_MAX) {
                        unsigned n = (unsigned)(i * 3 + a);
                        S.big.cand[pos] = ((unsigned long long)u << 32) | (unsigned long long)(~n);
                    }
                }
            }
        }
        __syncthreads();
        cnt = S.cnt_s;

        if (cnt > CAND_MAX) {
            for (int i = tid; i < NBIN; i += NTH) S.big.h.hist[i] = 0;
            __syncthreads();
            for (int a = 0; a < 3; a++) {
                const float* p = planes[a];
                for (int i = tid; i < HW; i += NTH) {
                    unsigned u = mapf(p[i]);
                    if ((int)(u >> 20) == T)
                        atomicAdd(&S.big.h.hist[(u >> 8) & 0xFFFu], 1u);
                }
            }
            __syncthreads();
            int T2, ab2;
            find_thr(S, KTOP - above, tid, T2, ab2);
            if (tid == 0) S.cnt_s = 0;
            __syncthreads();
            for (int a = 0; a < 3; a++) {
                const float* p = planes[a];
                for (int i = tid; i < HW; i += NTH) {
                    unsigned u = mapf(p[i]);
                    int bin = (int)(u >> 20);
                    if (bin > T || (bin == T && (int)((u >> 8) & 0xFFFu) >= T2)) {
                        int pos = atomicAdd(&S.cnt_s, 1);
                        if (pos < CAND_MAX) {
                            unsigned n = (unsigned)(i * 3 + a);
                            S.big.cand[pos] = ((unsigned long long)u << 32) | (unsigned long long)(~n);
                        }
                    }
                }
            }
            __syncthreads();
            cnt = S.cnt_s;
        }
        if (cnt > CAND_MAX) cnt = CAND_MAX;
    }

    // ---------- sort descending ----------
    if (cnt <= 1024) {
        // hybrid bitonic: 2 elems/thread in regs; j>=64 via smem,
        // j==32 in-thread, j<=16 via shfl. Global rule desc = ((i & k) == 0).
        for (int i = cnt + tid; i < 1024; i += NTH) S.big.cand[i] = 0ull;
        __syncthreads();

        const int base = wid << 6;
        const int i_lo = base + lane;
        const int i_hi = base + lane + 32;
        unsigned long long vlo = S.big.cand[i_lo];
        unsigned long long vhi = S.big.cand[i_hi];

        #define SHFL_STEP(k, j) do {                                               \
            unsigned long long plo = __shfl_xor_sync(0xFFFFFFFFu, vlo, (j));       \
            unsigned long long phi = __shfl_xor_sync(0xFFFFFFFFu, vhi, (j));       \
            bool low = ((lane & (j)) == 0);                                        \
            bool wl = (low == ((i_lo & (k)) == 0));                                \
            bool wh = (low == ((i_hi & (k)) == 0));                                \
            vlo = wl ? (vlo > plo ? vlo : plo) : (vlo < plo ? vlo : plo);          \
            vhi = wh ? (vhi > phi ? vhi : phi) : (vhi < phi ? vhi : phi);          \
        } while (0)

        #define INTHREAD_STEP(k) do {                                              \
            bool desc = ((i_lo & (k)) == 0);                                       \
            bool sw = desc ? (vlo < vhi) : (vlo > vhi);                            \
            if (sw) { unsigned long long t = vlo; vlo = vhi; vhi = t; }            \
        } while (0)

        #pragma unroll
        for (int k = 2; k <= 32; k <<= 1) {
            #pragma unroll
            for (int j = k >> 1; j >= 1; j >>= 1) SHFL_STEP(k, j);
        }
        INTHREAD_STEP(64);
        #pragma unroll
        for (int j = 16; j >= 1; j >>= 1) SHFL_STEP(64, j);

        #pragma unroll
        for (int k = 128; k <= 1024; k <<= 1) {
            S.big.cand[i_lo] = vlo;
            S.big.cand[i_hi] = vhi;
            for (int j = k >> 1; j >= 64; j >>= 1) {
                __syncthreads();
                #pragma unroll
                for (int t2 = 0; t2 < 2; t2++) {
                    int i = tid + t2 * 512;
                    int ixj = i ^ j;
                    if (ixj > i) {
                        unsigned long long a = S.big.cand[i], b = S.big.cand[ixj];
                        bool sw = ((i & k) == 0) ? (a < b) : (a > b);
                        if (sw) { S.big.cand[i] = b; S.big.cand[ixj] = a; }
                    }
                }
            }
            __syncthreads();
            vlo = S.big.cand[i_lo];
            vhi = S.big.cand[i_hi];
            INTHREAD_STEP(k);
            #pragma unroll
            for (int j = 16; j >= 1; j >>= 1) SHFL_STEP(k, j);
        }
        S.big.cand[i_lo] = vlo;
        S.big.cand[i_hi] = vhi;
        __syncthreads();
        #undef SHFL_STEP
        #undef INTHREAD_STEP
    } else {
        int M = 2048;
        while (M < cnt) M <<= 1;
        for (int i = cnt + tid; i < M; i += NTH) S.big.cand[i] = 0ull;
        __syncthreads();
        for (int k = 2; k <= M; k <<= 1) {
            for (int j = k >> 1; j > 0; j >>= 1) {
                for (int i = tid; i < M; i += NTH) {
                    int ixj = i ^ j;
                    if (ixj > i) {
                        unsigned long long a = S.big.cand[i], b = S.big.cand[ixj];
                        bool sw = ((i & k) == 0) ? (a < b) : (a > b);
                        if (sw) { S.big.cand[i] = b; S.big.cand[ixj] = a; }
                    }
                }
                __syncthreads();
            }
        }
    }

    // ---------- decode top-500, write boxes/scores/labels, stash in smem ----------
    long long tbase = (long long)((lev * 16 + img) * 7 + cls) * KTOP;
    float4* obox4 = (float4*)(out + tbase * 4);
    float* osc   = out + 672000 + tbase;
    float* olab  = out + 1008000 + tbase;

    {
        int r = tid;
        bool valid_bit = false;
        float bx1v = 0.0f, by1v = 0.0f, bx2v = 0.0f, by2v = 0.0f;
        if (r < KTOP) {
            unsigned long long key = S.big.cand[r];
            unsigned u = (unsigned)(key >> 32);
            unsigned n = ~((unsigned)key);
            float logit = unmapf(u);
            float score = __fdividef(1.0f, 1.0f + __expf(-logit));

            unsigned a = n % 3u;          // const-div (mul-shift)
            unsigned p = n / 3u;
            int sh = 6 - lev;             // W = 3 << sh
            unsigned y = (p >> sh) / 3u;  // p / W, const-div
            unsigned x = p - y * (unsigned)W;
            float sqv = (a == 0) ? 0.70710678118654752f : ((a == 1) ? 1.0f : 1.41421356237309505f);
            float wa = asize * sqv;
            float ha = asize / sqv;
            float cxa = ((float)x + 0.5f) * stride;
            float cya = ((float)y + 0.5f) * stride;

            size_t rb = (size_t)(img * 12 + a * 4) * HW + (size_t)p;
            float dx = regP[rb];
            float dy = regP[rb + HW];
            float dw = regP[rb + 2 * (size_t)HW];
            float dh = regP[rb + 3 * (size_t)HW];

            float cx = dx * wa + cxa;
            float cy = dy * ha + cya;
            float bw = __expf(dw) * wa;
            float bh = __expf(dh) * ha;
            bx1v = cx - 0.5f * bw; by1v = cy - 0.5f * bh;
            bx2v = cx + 0.5f * bw; by2v = cy + 0.5f * bh;

            obox4[r] = make_float4(bx1v, by1v, bx2v, by2v);
            osc[r] = score;
            olab[r] = (float)cls;
            valid_bit = (score > 0.05f);
        }
        unsigned b = __ballot_sync(0xFFFFFFFFu, valid_bit);
        if (lane == 0 && b)
            atomicOr(&S.keepw[tid >> 6], (unsigned long long)b << ((tid >> 5 & 1) * 32));
        __syncthreads();   // all cand reads done before sup (aliased) is zeroed below
        S.bx1[tid] = bx1v; S.by1[tid] = by1v; S.bx2[tid] = bx2v; S.by2[tid] = by2v;
        S.ar[tid]  = (bx2v - bx1v) * (by2v - by1v);
    }

    // ---------- zero sup matrix (reuses cand region) + hash init ----------
    for (int i = tid; i < KTOP * 8; i += NTH)
        (&S.big.sup[0][0])[i] = 0ull;
    for (int i = tid; i < 1024; i += NTH) S.cellcnt[i] = 0;
    __syncthreads();

    // ---------- spatial hash build ----------
    bool real = (tid < KTOP);
    float cx = 0.5f * (S.bx1[tid] + S.bx2[tid]);
    float cy = 0.5f * (S.by1[tid] + S.by2[tid]);
    float ext = fmaxf(S.bx2[tid] - S.bx1[tid], S.by2[tid] - S.by1[tid]);
    float rminx = real ? cx : 1e30f, rmaxx = real ? cx : -1e30f;
    float rminy = real ? cy : 1e30f, rmaxy = real ? cy : -1e30f;
    float rext  = real ? ext : 0.0f;
    rminx = wminf(rminx); rmaxx = wmaxf(rmaxx);
    rminy = wminf(rminy); rmaxy = wmaxf(rmaxy);
    rext  = wmaxf(rext);
    if (lane == 0) {
        S.warpred[wid][0] = rminx; S.warpred[wid][1] = rmaxx;
        S.warpred[wid][2] = rminy; S.warpred[wid][3] = rmaxy;
        S.warpred[wid][4] = rext;
    }
    __syncthreads();
    if (wid == 0) {
        float a0 = (lane < 16) ? S.warpred[lane][0] : 1e30f;
        float a1 = (lane < 16) ? S.warpred[lane][1] : -1e30f;
        float a2 = (lane < 16) ? S.warpred[lane][2] : 1e30f;
        float a3 = (lane < 16) ? S.warpred[lane][3] : -1e30f;
        float a4 = (lane < 16) ? S.warpred[lane][4] : 0.0f;
        a0 = wminf(a0); a1 = wmaxf(a1); a2 = wminf(a2); a3 = wmaxf(a3); a4 = wmaxf(a4);
        if (lane == 0) {
            S.red[0] = a0; S.red[1] = a1; S.red[2] = a2; S.red[3] = a3; S.red[4] = a4;
        }
    }
    __syncthreads();

    float minx = S.red[0], miny = S.red[2];
    float rx = S.red[1] - minx, ry = S.red[3] - miny;
    float cs = fmaxf(fmaxf(S.red[4], fmaxf(rx, ry) * (1.0f / 31.0f)), 1.0f) * 1.0001f;
    float inv_cs = 1.0f / cs;
    int ncx = min(32, (int)(rx * inv_cs) + 1);
    int ncy = min(32, (int)(ry * inv_cs) + 1);

    int cix = 0, ciy = 0;
    if (real) {
        cix = min(ncx - 1, max(0, (int)((cx - minx) * inv_cs)));
        ciy = min(ncy - 1, max(0, (int)((cy - miny) * inv_cs)));
        int cid = ciy * 32 + cix;
        S.cellid[tid] = (unsigned short)cid;
        atomicAdd(&S.cellcnt[cid], 1);
    }
    __syncthreads();

    // exclusive scan of 1024 cell counts (512 threads x 2)
    {
        int c0 = S.cellcnt[2 * tid], c1 = S.cellcnt[2 * tid + 1];
        int s = c0 + c1;
        int incl = s;
        #pragma unroll
        for (int o = 1; o < 32; o <<= 1) {
            int n = __shfl_up_sync(0xFFFFFFFFu, incl, o);
            if (lane >= o) incl += n;
        }
        if (lane == 31) S.wtot[wid] = incl;
        __syncthreads();
        if (wid == 0) {
            int t = (lane < 16) ? S.wtot[lane] : 0;
            int ti = t;
            #pragma unroll
            for (int o = 1; o < 32; o <<= 1) {
                int n = __shfl_up_sync(0xFFFFFFFFu, ti, o);
                if (lane >= o) ti += n;
            }
            if (lane < 16) S.wtot[lane] = ti - t;
        }
        __syncthreads();
        int woff = S.wtot[wid];
        int excl = woff + incl - s;
        S.cellstart[2 * tid] = excl;
        S.cellstart[2 * tid + 1] = excl + c0;
    }
    __syncthreads();

    if (real) {
        int pos = atomicAdd(&S.cellstart[S.cellid[tid]], 1);
        S.order[pos] = (unsigned short)tid;
    }
    __syncthreads();

    // sparse pair search: 3x3 neighbor cells, only j > i, set bit on IoU > 0.5
    if (real) {
        int i = tid;
        float ix1 = S.bx1[i], iy1 = S.by1[i], ix2 = S.bx2[i], iy2 = S.by2[i];
        float ai = S.ar[i];
        bool any = false;
        for (int dy = -1; dy <= 1; dy++) {
            int yy = ciy + dy;
            if (yy < 0 || yy >= ncy) continue;
            for (int dxl = -1; dxl <= 1; dxl++) {
                int xx = cix + dxl;
                if (xx < 0 || xx >= ncx) continue;
                int c = yy * 32 + xx;
                int e = S.cellstart[c];
                int b = e - S.cellcnt[c];
                for (int k = b; k < e; k++) {
                    int j = S.order[k];
                    if (j <= i) continue;
                    float xx1 = fmaxf(ix1, S.bx1[j]);
                    float yy1 = fmaxf(iy1, S.by1[j]);
                    float xx2 = fminf(ix2, S.bx2[j]);
                    float yy2 = fminf(iy2, S.by2[j]);
                    float inter = fmaxf(xx2 - xx1, 0.0f) * fmaxf(yy2 - yy1, 0.0f);
                    if (3.0f * inter > ai + S.ar[j]) {
                        atomicOr(&S.big.sup[i][j >> 6], 1ull << (j & 63));
                        any = true;
                    }
                }
            }
        }
        if (any) atomicOr(&S.supmark[i >> 6], 1ull << (i & 63));
    }
    __syncthreads();

    // sparse greedy: visit only alive suppressor rows in index order (exact)
    if (tid == 0) {
        unsigned long long dropped[8] = {0,0,0,0,0,0,0,0};
        for (int w = 0; w < 8; w++) {
            unsigned long long rem = S.supmark[w] & S.keepw[w];
            while (true) {
                unsigned long long r2 = rem & ~dropped[w];
                if (!r2) break;
                int b = __ffsll((long long)r2) - 1;
                rem &= ~(1ull << b);
                int i = (w << 6) + b;
                #pragma unroll
                for (int w2 = 0; w2 < 8; w2++) dropped[w2] |= S.big.sup[i][w2];
            }
        }
        #pragma unroll
        for (int w = 0; w < 8; w++) S.keepw[w] &= ~dropped[w];
    }
    __syncthreads();

    float* okeep = out + 840000 + tbase;
    for (int r = tid; r < KTOP; r += NTH)
        okeep[r] = ((S.keepw[r >> 6] >> (r & 63)) & 1ull) ? 1.0f : 0.0f;
    if (tid == 0) g_cnt[task] = 0;   // restore invariant for next graph replay
}

// ---------------- launcher ----------------
extern "C" void kernel_launch(void* const* d_in, const int* in_sizes, int n_in,
                              void* d_out, int out_size) {
    const float *cls3 = nullptr, *cls4 = nullptr, *cls5 = nullptr;
    const float *reg3 = nullptr, *reg4 = nullptr, *reg5 = nullptr;
    for (int i = 0; i < n_in; i++) {
        switch (in_sizes[i]) {
            case 14155776: cls3 = (const float*)d_in[i]; break;
            case 7077888:  reg3 = (const float*)d_in[i]; break;
            case 3538944:  cls4 = (const float*)d_in[i]; break;
            case 1769472:  reg4 = (const float*)d_in[i]; break;
            case 884736:   cls5 = (const float*)d_in[i]; break;
            case 442368:   reg5 = (const float*)d_in[i]; break;
        }
    }
    float* out = (float*)d_out;
    cudaFuncSetAttribute(k_fused, cudaFuncAttributeMaxDynamicSharedMemorySize,
                         (int)sizeof(Fused));
    k_scan<<<672, 512>>>(cls3, cls4, cls5);
    k_fused<<<NTASK, NTH, sizeof(Fused)>>>(cls3, cls4, cls5, reg3, reg4, reg5, out);
}